// round 4
// baseline (speedup 1.0000x reference)
#include <cuda_runtime.h>
#include <math_constants.h>

// Problem constants
#define NB   8192
#define NL   512
#define NC_  8
#define NK   1024
#define NSD  64
#define TAU_INV 14.285714285714285714f   // 1/0.07

// Output layout (float32): [0, NB*NL) quant, [NB*NL] commit, [NB*NL+1] contrastive,
// [NB*NL+2, +NB*NC_) indices-as-float
#define OUT_QUANT_N (NB*NL)

// ---------------- scratch (device globals; no allocation allowed) ----------------
__device__ float  g_zn[NB * NL];     // z row-normalized
__device__ float  g_qn[NB * NL];     // quant row-normalized
__device__ int    g_idx[NB * NC_];
__device__ float  g_e2[NC_ * NK];    // ||e||^2 per code
__device__ float  g_S[NB];           // sum_j exp((cos_ij - 1)/tau)
__device__ float  g_diag[NB];        // l_ii
__device__ double g_commit;          // sum (q-z)^2

// packed f32x2 FMA (ptxas will not auto-fuse; must come from PTX)
#define FMA2(d, a, b) asm("fma.rn.f32x2 %0, %1, %2, %0;" : "+l"(d) : "l"(a), "l"(b))

__device__ __forceinline__ float hsum2(unsigned long long u) {
    float lo, hi;
    asm("mov.b64 {%0,%1}, %2;" : "=f"(lo), "=f"(hi) : "l"(u));
    return lo + hi;
}

// ---------------- kernel 0: init accumulators + e2 ----------------
__global__ void init_kernel(const float* __restrict__ emb) {
    int i = blockIdx.x * blockDim.x + threadIdx.x;   // 8192 == NC_*NK == NB
    // e2 of code i (i = c*NK + k, contiguous 64 floats)
    const float4* p = (const float4*)(emb + (size_t)i * NSD);
    float s = 0.f;
#pragma unroll
    for (int u = 0; u < 16; u++) {
        float4 v = p[u];
        s += v.x * v.x + v.y * v.y + v.z * v.z + v.w * v.w;
    }
    g_e2[i] = s;
    g_S[i]  = 0.f;
    if (i == 0) g_commit = 0.0;
}

// ---------------- kernel 1: argmin over codebooks ----------------
// grid (NB/64, NC_), 256 threads. Block tile: 64 b-rows x 64-k chunks, f32x2 FMA over d.
__global__ __launch_bounds__(256) void argmin_kernel(const float* __restrict__ z,
                                                     const float* __restrict__ emb) {
    __shared__ float zs[64][66];
    __shared__ float es[64][66];
    __shared__ float rv[64][16];
    __shared__ int   ri[64][16];

    int c   = blockIdx.y;
    int b0  = blockIdx.x * 64;
    int tid = threadIdx.x;
    int tx  = tid & 15;      // k-slice: k = tx + 16*j
    int ty  = tid >> 4;      // b-slice: b = ty + 16*i

    // load z tile (64 rows x 64 cols of this codebook's slice)
#pragma unroll
    for (int u = 0; u < 8; u++) {
        int f = tid + u * 256;          // 0..2047 float2s
        int r = f >> 5, d2 = f & 31;
        float2 v = *(const float2*)(z + (size_t)(b0 + r) * NL + c * NSD + d2 * 2);
        *(float2*)&zs[r][d2 * 2] = v;
    }

    float best[4];
    int   bidx[4];
#pragma unroll
    for (int i = 0; i < 4; i++) { best[i] = CUDART_INF_F; bidx[i] = 0; }

    for (int kk = 0; kk < NK; kk += 64) {
        __syncthreads();
#pragma unroll
        for (int u = 0; u < 8; u++) {
            int f = tid + u * 256;
            int r = f >> 5, d2 = f & 31;
            float2 v = *(const float2*)(emb + ((size_t)c * NK + kk + r) * NSD + d2 * 2);
            *(float2*)&es[r][d2 * 2] = v;
        }
        __syncthreads();

        unsigned long long acc[4][4];
#pragma unroll
        for (int i = 0; i < 4; i++)
#pragma unroll
            for (int j = 0; j < 4; j++) acc[i][j] = 0ull;

#pragma unroll
        for (int dp = 0; dp < 32; dp++) {
            unsigned long long a2[4], b2[4];
#pragma unroll
            for (int i = 0; i < 4; i++)
                a2[i] = *(const unsigned long long*)&zs[ty + 16 * i][dp * 2];
#pragma unroll
            for (int j = 0; j < 4; j++)
                b2[j] = *(const unsigned long long*)&es[tx + 16 * j][dp * 2];
#pragma unroll
            for (int i = 0; i < 4; i++)
#pragma unroll
                for (int j = 0; j < 4; j++)
                    FMA2(acc[i][j], a2[i], b2[j]);
        }

#pragma unroll
        for (int j = 0; j < 4; j++) {
            int k = kk + tx + 16 * j;
            float h = 0.5f * __ldg(&g_e2[(c << 10) + k]);
#pragma unroll
            for (int i = 0; i < 4; i++) {
                float s = h - hsum2(acc[i][j]);   // argmin of e2/2 - <z,e>
                if (s < best[i]) { best[i] = s; bidx[i] = k; }
            }
        }
    }

    __syncthreads();
#pragma unroll
    for (int i = 0; i < 4; i++) {
        rv[ty + 16 * i][tx] = best[i];
        ri[ty + 16 * i][tx] = bidx[i];
    }
    __syncthreads();
    if (tid < 64) {
        float bv = rv[tid][0];
        int   bi = ri[tid][0];
#pragma unroll
        for (int t = 1; t < 16; t++) {
            float v = rv[tid][t]; int id = ri[tid][t];
            if (v < bv || (v == bv && id < bi)) { bv = v; bi = id; }
        }
        g_idx[(b0 + tid) * NC_ + c] = bi;
    }
}

// ---------------- kernel 2: gather + losses + row norms ----------------
// one block (128 threads) per row b
__global__ __launch_bounds__(128) void rowprep_kernel(const float* __restrict__ z,
                                                      const float* __restrict__ emb,
                                                      float* __restrict__ out) {
    int b = blockIdx.x, t = threadIdx.x;
    __shared__ float sred[4][4];
    __shared__ float sinv[2];
    __shared__ int   sk[8];

    if (t < 8) sk[t] = g_idx[b * NC_ + t];
    __syncthreads();

    float4 z4 = ((const float4*)z)[b * 128 + t];
    int c = t >> 4;
    int k = sk[c];
    float4 q4 = ((const float4*)emb)[((size_t)c * NK + k) * 16 + (t & 15)];

    float z2 = z4.x*z4.x + z4.y*z4.y + z4.z*z4.z + z4.w*z4.w;
    float q2 = q4.x*q4.x + q4.y*q4.y + q4.z*q4.z + q4.w*q4.w;
    float qz = z4.x*q4.x + z4.y*q4.y + z4.z*q4.z + z4.w*q4.w;
    float dx = q4.x - z4.x, dy = q4.y - z4.y, dz = q4.z - z4.z, dw = q4.w - z4.w;
    float dd = dx*dx + dy*dy + dz*dz + dw*dw;

#pragma unroll
    for (int o = 16; o > 0; o >>= 1) {
        z2 += __shfl_down_sync(0xffffffffu, z2, o);
        q2 += __shfl_down_sync(0xffffffffu, q2, o);
        qz += __shfl_down_sync(0xffffffffu, qz, o);
        dd += __shfl_down_sync(0xffffffffu, dd, o);
    }
    if ((t & 31) == 0) {
        int w = t >> 5;
        sred[w][0] = z2; sred[w][1] = q2; sred[w][2] = qz; sred[w][3] = dd;
    }
    __syncthreads();
    if (t == 0) {
        float Z2 = sred[0][0] + sred[1][0] + sred[2][0] + sred[3][0];
        float Q2 = sred[0][1] + sred[1][1] + sred[2][1] + sred[3][1];
        float QZ = sred[0][2] + sred[1][2] + sred[2][2] + sred[3][2];
        float DD = sred[0][3] + sred[1][3] + sred[2][3] + sred[3][3];
        float nz = fmaxf(sqrtf(Z2), 1e-12f);
        float nq = fmaxf(sqrtf(Q2), 1e-12f);
        sinv[0] = 1.f / nz;
        sinv[1] = 1.f / nq;
        g_diag[b] = QZ / (nz * nq) * TAU_INV;
        atomicAdd(&g_commit, (double)DD);
    }
    __syncthreads();

    float iz = sinv[0], iq = sinv[1];
    float4 zn4 = make_float4(z4.x*iz, z4.y*iz, z4.z*iz, z4.w*iz);
    float4 qn4 = make_float4(q4.x*iq, q4.y*iq, q4.z*iq, q4.w*iq);
    ((float4*)g_zn)[b * 128 + t] = zn4;
    ((float4*)g_qn)[b * 128 + t] = qn4;
    ((float4*)out )[b * 128 + t] = q4;      // quant_z_st == quant_z numerically
    if (t < 8) out[OUT_QUANT_N + 2 + b * NC_ + t] = (float)sk[t];
}

// ---------------- kernel 3: fused GEMM + exp row sums ----------------
// Block tile 128(m) x 64(n), BK=16, 256 threads, thread tile 8x4, f32x2 acc over k.
__global__ __launch_bounds__(256) void gemm_expsum_kernel() {
    __shared__ float As[128][18];
    __shared__ float Bs[64][18];
    __shared__ float red[128][17];

    int tid  = threadIdx.x;
    int row0 = blockIdx.y * 128;
    int col0 = blockIdx.x * 64;
    int tx   = tid & 15;     // n = tx + 16*j
    int ty   = tid >> 4;     // m = ty + 16*i

    unsigned long long acc[8][4];
#pragma unroll
    for (int i = 0; i < 8; i++)
#pragma unroll
        for (int j = 0; j < 4; j++) acc[i][j] = 0ull;

    for (int kk = 0; kk < NL; kk += 16) {
        // A tile: 128x16 = 512 float4
#pragma unroll
        for (int u = 0; u < 2; u++) {
            int f = tid + u * 256;
            int m = f >> 2, kq = (f & 3) << 2;
            float4 v = *(const float4*)(g_qn + (size_t)(row0 + m) * NL + kk + kq);
            *(float2*)&As[m][kq]     = make_float2(v.x, v.y);
            *(float2*)&As[m][kq + 2] = make_float2(v.z, v.w);
        }
        // B tile: 64x16 = 256 float4
        {
            int n = tid >> 2, kq = (tid & 3) << 2;
            float4 v = *(const float4*)(g_zn + (size_t)(col0 + n) * NL + kk + kq);
            *(float2*)&Bs[n][kq]     = make_float2(v.x, v.y);
            *(float2*)&Bs[n][kq + 2] = make_float2(v.z, v.w);
        }
        __syncthreads();

#pragma unroll
        for (int kp = 0; kp < 8; kp++) {
            unsigned long long a2[8], b2[4];
#pragma unroll
            for (int i = 0; i < 8; i++)
                a2[i] = *(const unsigned long long*)&As[ty + 16 * i][kp * 2];
#pragma unroll
            for (int j = 0; j < 4; j++)
                b2[j] = *(const unsigned long long*)&Bs[tx + 16 * j][kp * 2];
#pragma unroll
            for (int i = 0; i < 8; i++)
#pragma unroll
                for (int j = 0; j < 4; j++)
                    FMA2(acc[i][j], a2[i], b2[j]);
        }
        __syncthreads();
    }

    // epilogue: exp((cos-1)/tau), per-row partial sums
    float rowsum[8];
#pragma unroll
    for (int i = 0; i < 8; i++) {
        float s = 0.f;
#pragma unroll
        for (int j = 0; j < 4; j++) {
            float d0 = hsum2(acc[i][j]);
            s += __expf((d0 - 1.0f) * TAU_INV);
        }
        rowsum[i] = s;
    }
#pragma unroll
    for (int i = 0; i < 8; i++) red[ty + 16 * i][tx] = rowsum[i];
    __syncthreads();
    if (tid < 128) {
        float s = 0.f;
#pragma unroll
        for (int t = 0; t < 16; t++) s += red[tid][t];
        atomicAdd(&g_S[row0 + tid], s);
    }
}

// ---------------- kernel 4: finalize scalars ----------------
__global__ void finalize_kernel(float* __restrict__ out) {
    __shared__ double sd[512];
    int t = threadIdx.x;
    double local = 0.0;
    for (int i = t; i < NB; i += 512)
        local += (double)(TAU_INV + logf(g_S[i]) - g_diag[i]);
    sd[t] = local;
    __syncthreads();
    for (int s = 256; s > 0; s >>= 1) {
        if (t < s) sd[t] += sd[t + s];
        __syncthreads();
    }
    if (t == 0) {
        out[OUT_QUANT_N]     = (float)(2.0 * g_commit / (double)OUT_QUANT_N);
        out[OUT_QUANT_N + 1] = (float)(sd[0] / (double)NB);
    }
}

// ---------------- launch ----------------
extern "C" void kernel_launch(void* const* d_in, const int* in_sizes, int n_in,
                              void* d_out, int out_size) {
    const float* z   = (const float*)d_in[0];
    const float* emb = (const float*)d_in[1];
    float* out = (float*)d_out;

    init_kernel<<<NC_ * NK / 256, 256>>>(emb);
    argmin_kernel<<<dim3(NB / 64, NC_), 256>>>(z, emb);
    rowprep_kernel<<<NB, 128>>>(z, emb, out);
    gemm_expsum_kernel<<<dim3(NB / 64, NB / 128), 256>>>();
    finalize_kernel<<<1, 512>>>(out);
}

// round 14
// speedup vs baseline: 2.7824x; 2.7824x over previous
#include <cuda_runtime.h>
#include <cuda_bf16.h>
#include <math_constants.h>
#include <cstdint>

// Problem constants
#define NB   8192
#define NL   512
#define NC_  8
#define NK   1024
#define NSD  64
#define TAU_INV 14.285714285714285714f   // 1/0.07
#define OUT_QUANT_N (NB*NL)

#define KTOT   1536          // bf16x2 split: [qh|qh|ql] . [zh|zl|zh]
#define BM     128
#define BN     128
#define BK     64            // bf16 per k-chunk (128 bytes per row)
#define NCHUNKS (KTOT/BK)    // 24
#define STAGES  3
#define STAGE_BYTES 32768    // A 16KB + B 16KB
#define GEMM_SMEM (STAGES * STAGE_BYTES)

// ---------------- scratch (device globals; no allocation allowed) ----------------
__device__ __nv_bfloat16 g_a[NB * KTOT];   // [qh | qh | ql] rows of q_norm
__device__ __nv_bfloat16 g_b[NB * KTOT];   // [zh | zl | zh] rows of z_norm
__device__ int    g_idx[NB * NC_];
__device__ float  g_e2[NC_ * NK];
__device__ float  g_S[NB];                 // sum_j exp((cos_ij - 1)/tau)
__device__ float  g_diag[NB];              // l_ii (exact fp32)
__device__ double g_commit;

// packed f32x2 FMA for the argmin kernel
#define FMA2(d, a, b) asm("fma.rn.f32x2 %0, %1, %2, %0;" : "+l"(d) : "l"(a), "l"(b))

__device__ __forceinline__ float hsum2(unsigned long long u) {
    float lo, hi;
    asm("mov.b64 {%0,%1}, %2;" : "=f"(lo), "=f"(hi) : "l"(u));
    return lo + hi;
}

__device__ __forceinline__ uint32_t smem_u32(const void* p) {
    uint32_t a;
    asm("{ .reg .u64 t; cvta.to.shared.u64 t, %1; cvt.u32.u64 %0, t; }" : "=r"(a) : "l"(p));
    return a;
}
__device__ __forceinline__ void cpasync16(uint32_t s, const void* g) {
    asm volatile("cp.async.cg.shared.global [%0], [%1], 16;" :: "r"(s), "l"(g) : "memory");
}
__device__ __forceinline__ void ldmatrix_x4(uint32_t* r, uint32_t addr) {
    asm volatile("ldmatrix.sync.aligned.m8n8.x4.shared.b16 {%0,%1,%2,%3}, [%4];"
                 : "=r"(r[0]), "=r"(r[1]), "=r"(r[2]), "=r"(r[3]) : "r"(addr));
}
__device__ __forceinline__ void mma_bf16(float* d, const uint32_t* a,
                                         uint32_t b0, uint32_t b1) {
    asm volatile("mma.sync.aligned.m16n8k16.row.col.f32.bf16.bf16.f32 "
                 "{%0,%1,%2,%3}, {%4,%5,%6,%7}, {%8,%9}, {%0,%1,%2,%3};"
                 : "+f"(d[0]), "+f"(d[1]), "+f"(d[2]), "+f"(d[3])
                 : "r"(a[0]), "r"(a[1]), "r"(a[2]), "r"(a[3]), "r"(b0), "r"(b1));
}
__device__ __forceinline__ uint32_t sw128(uint32_t off) {
    return off ^ ((off >> 3) & 0x70);
}

// ---------------- kernel 0: init accumulators + e2 ----------------
__global__ void init_kernel(const float* __restrict__ emb) {
    int i = blockIdx.x * blockDim.x + threadIdx.x;   // 8192 == NC_*NK == NB
    const float4* p = (const float4*)(emb + (size_t)i * NSD);
    float s = 0.f;
#pragma unroll
    for (int u = 0; u < 16; u++) {
        float4 v = p[u];
        s += v.x * v.x + v.y * v.y + v.z * v.z + v.w * v.w;
    }
    g_e2[i] = s;
    g_S[i]  = 0.f;
    if (i == 0) g_commit = 0.0;
}

// ---------------- kernel 1: argmin over codebooks (fp32, exact) ----------------
__global__ __launch_bounds__(256) void argmin_kernel(const float* __restrict__ z,
                                                     const float* __restrict__ emb) {
    __shared__ float zs[64][66];
    __shared__ float es[64][66];
    __shared__ float rv[64][16];
    __shared__ int   ri[64][16];

    int c   = blockIdx.y;
    int b0  = blockIdx.x * 64;
    int tid = threadIdx.x;
    int tx  = tid & 15;
    int ty  = tid >> 4;

#pragma unroll
    for (int u = 0; u < 8; u++) {
        int f = tid + u * 256;
        int r = f >> 5, d2 = f & 31;
        float2 v = *(const float2*)(z + (size_t)(b0 + r) * NL + c * NSD + d2 * 2);
        *(float2*)&zs[r][d2 * 2] = v;
    }

    float best[4];
    int   bidx[4];
#pragma unroll
    for (int i = 0; i < 4; i++) { best[i] = CUDART_INF_F; bidx[i] = 0; }

    for (int kk = 0; kk < NK; kk += 64) {
        __syncthreads();
#pragma unroll
        for (int u = 0; u < 8; u++) {
            int f = tid + u * 256;
            int r = f >> 5, d2 = f & 31;
            float2 v = *(const float2*)(emb + ((size_t)c * NK + kk + r) * NSD + d2 * 2);
            *(float2*)&es[r][d2 * 2] = v;
        }
        __syncthreads();

        unsigned long long acc[4][4];
#pragma unroll
        for (int i = 0; i < 4; i++)
#pragma unroll
            for (int j = 0; j < 4; j++) acc[i][j] = 0ull;

#pragma unroll
        for (int dp = 0; dp < 32; dp++) {
            unsigned long long a2[4], b2[4];
#pragma unroll
            for (int i = 0; i < 4; i++)
                a2[i] = *(const unsigned long long*)&zs[ty + 16 * i][dp * 2];
#pragma unroll
            for (int j = 0; j < 4; j++)
                b2[j] = *(const unsigned long long*)&es[tx + 16 * j][dp * 2];
#pragma unroll
            for (int i = 0; i < 4; i++)
#pragma unroll
                for (int j = 0; j < 4; j++)
                    FMA2(acc[i][j], a2[i], b2[j]);
        }

#pragma unroll
        for (int j = 0; j < 4; j++) {
            int k = kk + tx + 16 * j;
            float h = 0.5f * __ldg(&g_e2[(c << 10) + k]);
#pragma unroll
            for (int i = 0; i < 4; i++) {
                float s = h - hsum2(acc[i][j]);
                if (s < best[i]) { best[i] = s; bidx[i] = k; }
            }
        }
    }

    __syncthreads();
#pragma unroll
    for (int i = 0; i < 4; i++) {
        rv[ty + 16 * i][tx] = best[i];
        ri[ty + 16 * i][tx] = bidx[i];
    }
    __syncthreads();
    if (tid < 64) {
        float bv = rv[tid][0];
        int   bi = ri[tid][0];
#pragma unroll
        for (int t = 1; t < 16; t++) {
            float v = rv[tid][t]; int id = ri[tid][t];
            if (v < bv || (v == bv && id < bi)) { bv = v; bi = id; }
        }
        g_idx[(b0 + tid) * NC_ + c] = bi;
    }
}

// ---------------- kernel 2: gather + losses + norms + bf16 hi/lo split ----------------
__device__ __forceinline__ void split_bf(float x, __nv_bfloat16& h, __nv_bfloat16& l) {
    h = __float2bfloat16_rn(x);
    l = __float2bfloat16_rn(x - __bfloat162float(h));
}
__device__ __forceinline__ uint2 pack4(__nv_bfloat16 a, __nv_bfloat16 b,
                                       __nv_bfloat16 c, __nv_bfloat16 d) {
    __nv_bfloat162 p0(a, b), p1(c, d);
    uint2 r;
    r.x = *(uint32_t*)&p0;
    r.y = *(uint32_t*)&p1;
    return r;
}

__global__ __launch_bounds__(128) void rowprep_kernel(const float* __restrict__ z,
                                                      const float* __restrict__ emb,
                                                      float* __restrict__ out) {
    int b = blockIdx.x, t = threadIdx.x;
    __shared__ float sred[4][4];
    __shared__ float sinv[2];
    __shared__ int   sk[8];

    if (t < 8) sk[t] = g_idx[b * NC_ + t];
    __syncthreads();

    float4 z4 = ((const float4*)z)[b * 128 + t];
    int c = t >> 4;
    int k = sk[c];
    float4 q4 = ((const float4*)emb)[((size_t)c * NK + k) * 16 + (t & 15)];

    float z2 = z4.x*z4.x + z4.y*z4.y + z4.z*z4.z + z4.w*z4.w;
    float q2 = q4.x*q4.x + q4.y*q4.y + q4.z*q4.z + q4.w*q4.w;
    float qz = z4.x*q4.x + z4.y*q4.y + z4.z*q4.z + z4.w*q4.w;
    float dx = q4.x - z4.x, dy = q4.y - z4.y, dz = q4.z - z4.z, dw = q4.w - z4.w;
    float dd = dx*dx + dy*dy + dz*dz + dw*dw;

#pragma unroll
    for (int o = 16; o > 0; o >>= 1) {
        z2 += __shfl_down_sync(0xffffffffu, z2, o);
        q2 += __shfl_down_sync(0xffffffffu, q2, o);
        qz += __shfl_down_sync(0xffffffffu, qz, o);
        dd += __shfl_down_sync(0xffffffffu, dd, o);
    }
    if ((t & 31) == 0) {
        int w = t >> 5;
        sred[w][0] = z2; sred[w][1] = q2; sred[w][2] = qz; sred[w][3] = dd;
    }
    __syncthreads();
    if (t == 0) {
        float Z2 = sred[0][0] + sred[1][0] + sred[2][0] + sred[3][0];
        float Q2 = sred[0][1] + sred[1][1] + sred[2][1] + sred[3][1];
        float QZ = sred[0][2] + sred[1][2] + sred[2][2] + sred[3][2];
        float DD = sred[0][3] + sred[1][3] + sred[2][3] + sred[3][3];
        float nz = fmaxf(sqrtf(Z2), 1e-12f);
        float nq = fmaxf(sqrtf(Q2), 1e-12f);
        sinv[0] = 1.f / nz;
        sinv[1] = 1.f / nq;
        g_diag[b] = QZ / (nz * nq) * TAU_INV;
        atomicAdd(&g_commit, (double)DD);
    }
    __syncthreads();

    float iz = sinv[0], iq = sinv[1];
    float4 zn4 = make_float4(z4.x*iz, z4.y*iz, z4.z*iz, z4.w*iz);
    float4 qn4 = make_float4(q4.x*iq, q4.y*iq, q4.z*iq, q4.w*iq);

    __nv_bfloat16 qh[4], ql[4], zh[4], zl[4];
    split_bf(qn4.x, qh[0], ql[0]); split_bf(qn4.y, qh[1], ql[1]);
    split_bf(qn4.z, qh[2], ql[2]); split_bf(qn4.w, qh[3], ql[3]);
    split_bf(zn4.x, zh[0], zl[0]); split_bf(zn4.y, zh[1], zl[1]);
    split_bf(zn4.z, zh[2], zl[2]); split_bf(zn4.w, zl[3] = __nv_bfloat16(), zl[3]);
    // (fix the w-lane split explicitly below to avoid any ambiguity)
    zh[3] = __float2bfloat16_rn(zn4.w);
    zl[3] = __float2bfloat16_rn(zn4.w - __bfloat162float(zh[3]));

    // rows of length KTOT=1536 -> 384 uint2 (4 bf16 each). t covers elems 4t..4t+3.
    uint2* arow = (uint2*)(g_a + (size_t)b * KTOT);
    uint2* brow = (uint2*)(g_b + (size_t)b * KTOT);
    uint2 qhp = pack4(qh[0], qh[1], qh[2], qh[3]);
    uint2 qlp = pack4(ql[0], ql[1], ql[2], ql[3]);
    uint2 zhp = pack4(zh[0], zh[1], zh[2], zh[3]);
    uint2 zlp = pack4(zl[0], zl[1], zl[2], zl[3]);
    arow[t]       = qhp;   // chunk 0: qh
    arow[128 + t] = qhp;   // chunk 1: qh
    arow[256 + t] = qlp;   // chunk 2: ql
    brow[t]       = zhp;   // chunk 0: zh
    brow[128 + t] = zlp;   // chunk 1: zl
    brow[256 + t] = zhp;   // chunk 2: zh

    ((float4*)out)[b * 128 + t] = q4;      // quant_z_st == quant_z numerically
    if (t < 8) out[OUT_QUANT_N + 2 + b * NC_ + t] = (float)sk[t];
}

// ---------------- kernel 3: bf16 mma.sync GEMM + fused exp row sums ----------------
// CTA 128x128, 8 warps (4m x 2n), warp tile 32x64, BK=64, 3-stage cp.async.
__device__ __forceinline__ void load_stage(uint32_t sb, int chunk, int stage,
                                           int row0, int col0, int tid) {
    const __nv_bfloat16* A = g_a;
    const __nv_bfloat16* B = g_b;
    uint32_t s0 = sb + stage * STAGE_BYTES;
#pragma unroll
    for (int i = 0; i < 8; i++) {
        int u = tid + i * 256;              // 0..2047 16B units
        int r   = (u >> 3) & 127;           // row within tile
        int seg = u & 7;                    // 16B unit within 128B row
        uint32_t off = (uint32_t)(r * 128 + seg * 16);
        uint32_t dst = s0 + (u < 1024 ? 0 : 16384) + sw128(off);
        const __nv_bfloat16* src = (u < 1024)
            ? A + (size_t)(row0 + r) * KTOT + chunk * BK + seg * 8
            : B + (size_t)(col0 + r) * KTOT + chunk * BK + seg * 8;
        cpasync16(dst, src);
    }
}

__global__ __launch_bounds__(256, 2) void gemm_mma_kernel() {
    extern __shared__ __align__(1024) char dsm[];
    const int tid  = threadIdx.x;
    const int lane = tid & 31;
    const int wid  = tid >> 5;
    const int wm   = (wid & 3) * 32;       // warp m offset
    const int wn   = (wid >> 2) * 64;      // warp n offset
    const int row0 = blockIdx.y * BM;
    const int col0 = blockIdx.x * BN;
    const uint32_t sb = smem_u32(dsm);

    float acc[2][8][4];
#pragma unroll
    for (int i = 0; i < 2; i++)
#pragma unroll
        for (int j = 0; j < 8; j++)
#pragma unroll
            for (int c = 0; c < 4; c++) acc[i][j][c] = 0.f;

    // prologue
    load_stage(sb, 0, 0, row0, col0, tid);
    asm volatile("cp.async.commit_group;" ::: "memory");
    load_stage(sb, 1, 1, row0, col0, tid);
    asm volatile("cp.async.commit_group;" ::: "memory");

    const int lrow = lane & 15;            // ldmatrix row-in-tile
    const int lcol = (lane >> 4) * 16;     // ldmatrix 16B column half

    for (int c = 0; c < NCHUNKS; c++) {
        const int s = c % STAGES;
        if (c == NCHUNKS - 1) asm volatile("cp.async.wait_group 0;" ::: "memory");
        else                  asm volatile("cp.async.wait_group 1;" ::: "memory");
        __syncthreads();

        if (c + 2 < NCHUNKS) {
            load_stage(sb, c + 2, (c + 2) % STAGES, row0, col0, tid);
            asm volatile("cp.async.commit_group;" ::: "memory");
        }

        uint32_t aS = sb + s * STAGE_BYTES;
        uint32_t bS = aS + 16384;
#pragma unroll
        for (int ks = 0; ks < 4; ks++) {   // 4 x k16 per 64-chunk
            uint32_t a[2][4], b[4][4];
#pragma unroll
            for (int i = 0; i < 2; i++) {
                uint32_t off = (uint32_t)((wm + i * 16 + lrow) * 128 + ks * 32 + lcol);
                ldmatrix_x4(a[i], aS + sw128(off));
            }
#pragma unroll
            for (int j = 0; j < 4; j++) {
                uint32_t off = (uint32_t)((wn + j * 16 + lrow) * 128 + ks * 32 + lcol);
                ldmatrix_x4(b[j], bS + sw128(off));
            }
#pragma unroll
            for (int i = 0; i < 2; i++)
#pragma unroll
                for (int j = 0; j < 4; j++) {
                    mma_bf16(acc[i][2 * j],     a[i], b[j][0], b[j][2]);
                    mma_bf16(acc[i][2 * j + 1], a[i], b[j][1], b[j][3]);
                }
        }
        __syncthreads();
    }

    // epilogue: exp((cos-1)/tau), per-row reduce (4 lanes share a row), atomicAdd
#pragma unroll
    for (int i = 0; i < 2; i++) {
#pragma unroll
        for (int h = 0; h < 2; h++) {
            float v = 0.f;
#pragma unroll
            for (int j = 0; j < 8; j++) {
                v += __expf((acc[i][j][2 * h]     - 1.0f) * TAU_INV);
                v += __expf((acc[i][j][2 * h + 1] - 1.0f) * TAU_INV);
            }
            v += __shfl_xor_sync(0xffffffffu, v, 1);
            v += __shfl_xor_sync(0xffffffffu, v, 2);
            if ((lane & 3) == 0) {
                int r = row0 + wm + i * 16 + (lane >> 2) + h * 8;
                atomicAdd(&g_S[r], v);
            }
        }
    }
}

// ---------------- kernel 4: finalize scalars ----------------
__global__ void finalize_kernel(float* __restrict__ out) {
    __shared__ double sd[512];
    int t = threadIdx.x;
    double local = 0.0;
    for (int i = t; i < NB; i += 512)
        local += (double)(TAU_INV + logf(g_S[i]) - g_diag[i]);
    sd[t] = local;
    __syncthreads();
    for (int s = 256; s > 0; s >>= 1) {
        if (t < s) sd[t] += sd[t + s];
        __syncthreads();
    }
    if (t == 0) {
        out[OUT_QUANT_N]     = (float)(2.0 * g_commit / (double)OUT_QUANT_N);
        out[OUT_QUANT_N + 1] = (float)(sd[0] / (double)NB);
    }
}

// ---------------- launch ----------------
extern "C" void kernel_launch(void* const* d_in, const int* in_sizes, int n_in,
                              void* d_out, int out_size) {
    const float* z   = (const float*)d_in[0];
    const float* emb = (const float*)d_in[1];
    float* out = (float*)d_out;

    cudaFuncSetAttribute(gemm_mma_kernel,
                         cudaFuncAttributeMaxDynamicSharedMemorySize, GEMM_SMEM);

    init_kernel<<<NC_ * NK / 256, 256>>>(emb);
    argmin_kernel<<<dim3(NB / 64, NC_), 256>>>(z, emb);
    rowprep_kernel<<<NB, 128>>>(z, emb, out);
    gemm_mma_kernel<<<dim3(NB / BN, NB / BM), 256, GEMM_SMEM>>>();
    finalize_kernel<<<1, 512>>>(out);
}

// round 15
// speedup vs baseline: 4.9023x; 1.7619x over previous
#include <cuda_runtime.h>
#include <cuda_fp16.h>
#include <math_constants.h>
#include <cstdint>

// Problem constants
#define NB   8192
#define NL   512
#define NC_  8
#define NK   1024
#define NSD  64
#define TAU_INV 14.285714285714285714f   // 1/0.07
#define OUT_QUANT_N (NB*NL)

#define KTOT   512           // single-term fp16 GEMM: qh . zh
#define BM     128
#define BN     128
#define BK     64            // fp16 per k-chunk (128 bytes per row)
#define NCHUNKS (KTOT/BK)    // 8
#define STAGES  3
#define STAGE_BYTES 32768    // A 16KB + B 16KB
#define GEMM_SMEM (STAGES * STAGE_BYTES)

// ---------------- scratch (device globals; no allocation allowed) ----------------
__device__ __half g_a[NB * KTOT];   // fp16(q_norm)
__device__ __half g_b[NB * KTOT];   // fp16(z_norm)
__device__ int    g_idx[NB * NC_];
__device__ float  g_e2[NC_ * NK];
__device__ float  g_S[NB];          // sum_j exp((cos_ij - 1)/tau)
__device__ float  g_diag[NB];       // l_ii (exact fp32)
__device__ double g_commit;

// packed f32x2 FMA for the argmin kernel
#define FMA2(d, a, b) asm("fma.rn.f32x2 %0, %1, %2, %0;" : "+l"(d) : "l"(a), "l"(b))

__device__ __forceinline__ float hsum2(unsigned long long u) {
    float lo, hi;
    asm("mov.b64 {%0,%1}, %2;" : "=f"(lo), "=f"(hi) : "l"(u));
    return lo + hi;
}

__device__ __forceinline__ uint32_t smem_u32(const void* p) {
    uint32_t a;
    asm("{ .reg .u64 t; cvta.to.shared.u64 t, %1; cvt.u32.u64 %0, t; }" : "=r"(a) : "l"(p));
    return a;
}
__device__ __forceinline__ void cpasync16(uint32_t s, const void* g) {
    asm volatile("cp.async.cg.shared.global [%0], [%1], 16;" :: "r"(s), "l"(g) : "memory");
}
__device__ __forceinline__ void ldmatrix_x4(uint32_t* r, uint32_t addr) {
    asm volatile("ldmatrix.sync.aligned.m8n8.x4.shared.b16 {%0,%1,%2,%3}, [%4];"
                 : "=r"(r[0]), "=r"(r[1]), "=r"(r[2]), "=r"(r[3]) : "r"(addr));
}
__device__ __forceinline__ void mma_fp16(float* d, const uint32_t* a,
                                         uint32_t b0, uint32_t b1) {
    asm volatile("mma.sync.aligned.m16n8k16.row.col.f32.f16.f16.f32 "
                 "{%0,%1,%2,%3}, {%4,%5,%6,%7}, {%8,%9}, {%0,%1,%2,%3};"
                 : "+f"(d[0]), "+f"(d[1]), "+f"(d[2]), "+f"(d[3])
                 : "r"(a[0]), "r"(a[1]), "r"(a[2]), "r"(a[3]), "r"(b0), "r"(b1));
}
__device__ __forceinline__ uint32_t sw128(uint32_t off) {
    return off ^ ((off >> 3) & 0x70);
}

// ---------------- kernel 0: init accumulators + e2 ----------------
__global__ void init_kernel(const float* __restrict__ emb) {
    int i = blockIdx.x * blockDim.x + threadIdx.x;   // 8192 == NC_*NK == NB
    const float4* p = (const float4*)(emb + (size_t)i * NSD);
    float s = 0.f;
#pragma unroll
    for (int u = 0; u < 16; u++) {
        float4 v = p[u];
        s += v.x * v.x + v.y * v.y + v.z * v.z + v.w * v.w;
    }
    g_e2[i] = s;
    g_S[i]  = 0.f;
    if (i == 0) g_commit = 0.0;
}

// ---------------- kernel 1: argmin over codebooks (fp32, exact) ----------------
__global__ __launch_bounds__(256) void argmin_kernel(const float* __restrict__ z,
                                                     const float* __restrict__ emb) {
    __shared__ float zs[64][66];
    __shared__ float es[64][66];
    __shared__ float rv[64][16];
    __shared__ int   ri[64][16];

    int c   = blockIdx.y;
    int b0  = blockIdx.x * 64;
    int tid = threadIdx.x;
    int tx  = tid & 15;
    int ty  = tid >> 4;

#pragma unroll
    for (int u = 0; u < 8; u++) {
        int f = tid + u * 256;
        int r = f >> 5, d2 = f & 31;
        float2 v = *(const float2*)(z + (size_t)(b0 + r) * NL + c * NSD + d2 * 2);
        *(float2*)&zs[r][d2 * 2] = v;
    }

    float best[4];
    int   bidx[4];
#pragma unroll
    for (int i = 0; i < 4; i++) { best[i] = CUDART_INF_F; bidx[i] = 0; }

    for (int kk = 0; kk < NK; kk += 64) {
        __syncthreads();
#pragma unroll
        for (int u = 0; u < 8; u++) {
            int f = tid + u * 256;
            int r = f >> 5, d2 = f & 31;
            float2 v = *(const float2*)(emb + ((size_t)c * NK + kk + r) * NSD + d2 * 2);
            *(float2*)&es[r][d2 * 2] = v;
        }
        __syncthreads();

        unsigned long long acc[4][4];
#pragma unroll
        for (int i = 0; i < 4; i++)
#pragma unroll
            for (int j = 0; j < 4; j++) acc[i][j] = 0ull;

#pragma unroll
        for (int dp = 0; dp < 32; dp++) {
            unsigned long long a2[4], b2[4];
#pragma unroll
            for (int i = 0; i < 4; i++)
                a2[i] = *(const unsigned long long*)&zs[ty + 16 * i][dp * 2];
#pragma unroll
            for (int j = 0; j < 4; j++)
                b2[j] = *(const unsigned long long*)&es[tx + 16 * j][dp * 2];
#pragma unroll
            for (int i = 0; i < 4; i++)
#pragma unroll
                for (int j = 0; j < 4; j++)
                    FMA2(acc[i][j], a2[i], b2[j]);
        }

#pragma unroll
        for (int j = 0; j < 4; j++) {
            int k = kk + tx + 16 * j;
            float h = 0.5f * __ldg(&g_e2[(c << 10) + k]);
#pragma unroll
            for (int i = 0; i < 4; i++) {
                float s = h - hsum2(acc[i][j]);
                if (s < best[i]) { best[i] = s; bidx[i] = k; }
            }
        }
    }

    __syncthreads();
#pragma unroll
    for (int i = 0; i < 4; i++) {
        rv[ty + 16 * i][tx] = best[i];
        ri[ty + 16 * i][tx] = bidx[i];
    }
    __syncthreads();
    if (tid < 64) {
        float bv = rv[tid][0];
        int   bi = ri[tid][0];
#pragma unroll
        for (int t = 1; t < 16; t++) {
            float v = rv[tid][t]; int id = ri[tid][t];
            if (v < bv || (v == bv && id < bi)) { bv = v; bi = id; }
        }
        g_idx[(b0 + tid) * NC_ + c] = bi;
    }
}

// ---------------- kernel 2: gather + losses + norms + fp16 operands ----------------
__global__ __launch_bounds__(128) void rowprep_kernel(const float* __restrict__ z,
                                                      const float* __restrict__ emb,
                                                      float* __restrict__ out) {
    int b = blockIdx.x, t = threadIdx.x;
    __shared__ float sred[4][4];
    __shared__ float sinv[2];
    __shared__ int   sk[8];

    if (t < 8) sk[t] = g_idx[b * NC_ + t];
    __syncthreads();

    float4 z4 = ((const float4*)z)[b * 128 + t];
    int c = t >> 4;
    int k = sk[c];
    float4 q4 = ((const float4*)emb)[((size_t)c * NK + k) * 16 + (t & 15)];

    float z2 = z4.x*z4.x + z4.y*z4.y + z4.z*z4.z + z4.w*z4.w;
    float q2 = q4.x*q4.x + q4.y*q4.y + q4.z*q4.z + q4.w*q4.w;
    float qz = z4.x*q4.x + z4.y*q4.y + z4.z*q4.z + z4.w*q4.w;
    float dx = q4.x - z4.x, dy = q4.y - z4.y, dz = q4.z - z4.z, dw = q4.w - z4.w;
    float dd = dx*dx + dy*dy + dz*dz + dw*dw;

#pragma unroll
    for (int o = 16; o > 0; o >>= 1) {
        z2 += __shfl_down_sync(0xffffffffu, z2, o);
        q2 += __shfl_down_sync(0xffffffffu, q2, o);
        qz += __shfl_down_sync(0xffffffffu, qz, o);
        dd += __shfl_down_sync(0xffffffffu, dd, o);
    }
    if ((t & 31) == 0) {
        int w = t >> 5;
        sred[w][0] = z2; sred[w][1] = q2; sred[w][2] = qz; sred[w][3] = dd;
    }
    __syncthreads();
    if (t == 0) {
        float Z2 = sred[0][0] + sred[1][0] + sred[2][0] + sred[3][0];
        float Q2 = sred[0][1] + sred[1][1] + sred[2][1] + sred[3][1];
        float QZ = sred[0][2] + sred[1][2] + sred[2][2] + sred[3][2];
        float DD = sred[0][3] + sred[1][3] + sred[2][3] + sred[3][3];
        float nz = fmaxf(sqrtf(Z2), 1e-12f);
        float nq = fmaxf(sqrtf(Q2), 1e-12f);
        sinv[0] = 1.f / nz;
        sinv[1] = 1.f / nq;
        g_diag[b] = QZ / (nz * nq) * TAU_INV;
        atomicAdd(&g_commit, (double)DD);
    }
    __syncthreads();

    float iz = sinv[0], iq = sinv[1];

    __half2 qp0(__float2half_rn(q4.x * iq), __float2half_rn(q4.y * iq));
    __half2 qp1(__float2half_rn(q4.z * iq), __float2half_rn(q4.w * iq));
    __half2 zp0(__float2half_rn(z4.x * iz), __float2half_rn(z4.y * iz));
    __half2 zp1(__float2half_rn(z4.z * iz), __float2half_rn(z4.w * iz));

    uint2 qa, zb;
    qa.x = *(uint32_t*)&qp0; qa.y = *(uint32_t*)&qp1;
    zb.x = *(uint32_t*)&zp0; zb.y = *(uint32_t*)&zp1;
    ((uint2*)(g_a + (size_t)b * KTOT))[t] = qa;   // elems 4t..4t+3 (KTOT=512, t<128)
    ((uint2*)(g_b + (size_t)b * KTOT))[t] = zb;

    ((float4*)out)[b * 128 + t] = q4;      // quant_z_st == quant_z numerically
    if (t < 8) out[OUT_QUANT_N + 2 + b * NC_ + t] = (float)sk[t];
}

// ---------------- kernel 3: fp16 mma.sync GEMM (K=512) + fused exp row sums ----------------
// CTA 128x128, 8 warps (4m x 2n), warp tile 32x64, BK=64, 3-stage cp.async.
__device__ __forceinline__ void load_stage(uint32_t sb, int chunk, int stage,
                                           int row0, int col0, int tid) {
    const __half* A = g_a;
    const __half* B = g_b;
    uint32_t s0 = sb + stage * STAGE_BYTES;
#pragma unroll
    for (int i = 0; i < 8; i++) {
        int u = tid + i * 256;              // 0..2047 16B units
        int r   = (u >> 3) & 127;           // row within tile
        int seg = u & 7;                    // 16B unit within 128B row
        uint32_t off = (uint32_t)(r * 128 + seg * 16);
        uint32_t dst = s0 + (u < 1024 ? 0 : 16384) + sw128(off);
        const __half* src = (u < 1024)
            ? A + (size_t)(row0 + r) * KTOT + chunk * BK + seg * 8
            : B + (size_t)(col0 + r) * KTOT + chunk * BK + seg * 8;
        cpasync16(dst, src);
    }
}

__global__ __launch_bounds__(256, 2) void gemm_mma_kernel() {
    extern __shared__ __align__(1024) char dsm[];
    const int tid  = threadIdx.x;
    const int lane = tid & 31;
    const int wid  = tid >> 5;
    const int wm   = (wid & 3) * 32;       // warp m offset
    const int wn   = (wid >> 2) * 64;      // warp n offset
    const int row0 = blockIdx.y * BM;
    const int col0 = blockIdx.x * BN;
    const uint32_t sb = smem_u32(dsm);

    float acc[2][8][4];
#pragma unroll
    for (int i = 0; i < 2; i++)
#pragma unroll
        for (int j = 0; j < 8; j++)
#pragma unroll
            for (int c = 0; c < 4; c++) acc[i][j][c] = 0.f;

    // prologue
    load_stage(sb, 0, 0, row0, col0, tid);
    asm volatile("cp.async.commit_group;" ::: "memory");
    load_stage(sb, 1, 1, row0, col0, tid);
    asm volatile("cp.async.commit_group;" ::: "memory");

    const int lrow = lane & 15;            // ldmatrix row-in-tile
    const int lcol = (lane >> 4) * 16;     // ldmatrix 16B column half

    for (int c = 0; c < NCHUNKS; c++) {
        const int s = c % STAGES;
        if (c == NCHUNKS - 1) asm volatile("cp.async.wait_group 0;" ::: "memory");
        else                  asm volatile("cp.async.wait_group 1;" ::: "memory");
        __syncthreads();
        // NOTE: single barrier per chunk. Safe because the load below targets
        // stage (c+2)%3 == stage (c-1)%3, whose last readers (iteration c-1)
        // all passed this barrier already.
        if (c + 2 < NCHUNKS) {
            load_stage(sb, c + 2, (c + 2) % STAGES, row0, col0, tid);
            asm volatile("cp.async.commit_group;" ::: "memory");
        }

        uint32_t aS = sb + s * STAGE_BYTES;
        uint32_t bS = aS + 16384;
#pragma unroll
        for (int ks = 0; ks < 4; ks++) {   // 4 x k16 per 64-chunk
            uint32_t a[2][4], b[4][4];
#pragma unroll
            for (int i = 0; i < 2; i++) {
                uint32_t off = (uint32_t)((wm + i * 16 + lrow) * 128 + ks * 32 + lcol);
                ldmatrix_x4(a[i], aS + sw128(off));
            }
#pragma unroll
            for (int j = 0; j < 4; j++) {
                uint32_t off = (uint32_t)((wn + j * 16 + lrow) * 128 + ks * 32 + lcol);
                ldmatrix_x4(b[j], bS + sw128(off));
            }
#pragma unroll
            for (int i = 0; i < 2; i++)
#pragma unroll
                for (int j = 0; j < 4; j++) {
                    mma_fp16(acc[i][2 * j],     a[i], b[j][0], b[j][2]);
                    mma_fp16(acc[i][2 * j + 1], a[i], b[j][1], b[j][3]);
                }
        }
    }

    // epilogue: exp((cos-1)/tau), per-row reduce (4 lanes share a row), atomicAdd
#pragma unroll
    for (int i = 0; i < 2; i++) {
#pragma unroll
        for (int h = 0; h < 2; h++) {
            float v = 0.f;
#pragma unroll
            for (int j = 0; j < 8; j++) {
                v += __expf((acc[i][j][2 * h]     - 1.0f) * TAU_INV);
                v += __expf((acc[i][j][2 * h + 1] - 1.0f) * TAU_INV);
            }
            v += __shfl_xor_sync(0xffffffffu, v, 1);
            v += __shfl_xor_sync(0xffffffffu, v, 2);
            if ((lane & 3) == 0) {
                int r = row0 + wm + i * 16 + (lane >> 2) + h * 8;
                atomicAdd(&g_S[r], v);
            }
        }
    }
}

// ---------------- kernel 4: finalize scalars ----------------
__global__ void finalize_kernel(float* __restrict__ out) {
    __shared__ double sd[512];
    int t = threadIdx.x;
    double local = 0.0;
    for (int i = t; i < NB; i += 512)
        local += (double)(TAU_INV + logf(g_S[i]) - g_diag[i]);
    sd[t] = local;
    __syncthreads();
    for (int s = 256; s > 0; s >>= 1) {
        if (t < s) sd[t] += sd[t + s];
        __syncthreads();
    }
    if (t == 0) {
        out[OUT_QUANT_N]     = (float)(2.0 * g_commit / (double)OUT_QUANT_N);
        out[OUT_QUANT_N + 1] = (float)(sd[0] / (double)NB);
    }
}

// ---------------- launch ----------------
extern "C" void kernel_launch(void* const* d_in, const int* in_sizes, int n_in,
                              void* d_out, int out_size) {
    const float* z   = (const float*)d_in[0];
    const float* emb = (const float*)d_in[1];
    float* out = (float*)d_out;

    cudaFuncSetAttribute(gemm_mma_kernel,
                         cudaFuncAttributeMaxDynamicSharedMemorySize, GEMM_SMEM);

    init_kernel<<<NC_ * NK / 256, 256>>>(emb);
    argmin_kernel<<<dim3(NB / 64, NC_), 256>>>(z, emb);
    rowprep_kernel<<<NB, 128>>>(z, emb, out);
    gemm_mma_kernel<<<dim3(NB / BN, NB / BM), 256, GEMM_SMEM>>>();
    finalize_kernel<<<1, 512>>>(out);
}